// round 15
// baseline (speedup 1.0000x reference)
#include <cuda_runtime.h>
#include <cstdint>
#include <cstddef>

// Problem constants (C_ prefix to avoid collisions with local identifiers)
#define C_HID 128
#define C_INT 64
#define C_BAS 8
#define C_NR 6
#define C_NSBF 42      // NS*NR = 7*6
#define C_NE 200000

// Scratch buffers (device globals; no allocation allowed)
__device__ __align__(128) float g_bufA[C_NE * C_HID];
__device__ __align__(128) float g_bufB[C_NE * C_HID];
__device__ __align__(128) float g_bufC[C_NE * C_INT];
__device__ __align__(128) float g_bufD[C_NE * C_INT];

__device__ __forceinline__ float swishf(float v) {
    return v / (1.0f + __expf(-v));
}

__device__ __forceinline__ uint32_t f2tf(float f) {
    uint32_t r;
    asm("cvt.rna.tf32.f32 %0, %1;" : "=r"(r) : "f"(f));
    return r;
}

__device__ __forceinline__ void mma_tf32(float c[4], const uint32_t a[4],
                                         uint32_t b0, uint32_t b1) {
    asm volatile(
        "mma.sync.aligned.m16n8k8.row.col.f32.tf32.tf32.f32 "
        "{%0,%1,%2,%3}, {%4,%5,%6,%7}, {%8,%9}, {%0,%1,%2,%3};"
        : "+f"(c[0]), "+f"(c[1]), "+f"(c[2]), "+f"(c[3])
        : "r"(a[0]), "r"(a[1]), "r"(a[2]), "r"(a[3]), "r"(b0), "r"(b1));
}

__device__ __forceinline__ void ldsm_x4(uint32_t a[4], uint32_t byte_addr) {
    asm volatile(
        "ldmatrix.sync.aligned.m8n8.x4.shared.b16 {%0,%1,%2,%3}, [%4];"
        : "=r"(a[0]), "=r"(a[1]), "=r"(a[2]), "=r"(a[3])
        : "r"(byte_addr));
}

// ---------------------------------------------------------------------------
// TF32 GEMM v5: v4 + 2-deep fragment prefetch (targets issue=42% measured).
// W fully resident; A double-buffered; ldmatrix.x4 A-fragments; 2m x 4n warps.
// epi: (+bias) -> (swish) -> (*rbf_e) -> (+addsrc). In-place A==out safe.
// ---------------------------------------------------------------------------
template<int N, int K, bool BIAS, bool ACT, bool ADD, bool RBF>
__global__ __launch_bounds__(256, 2)
void mma_gemm5(const float* __restrict__ A, const float* __restrict__ W,
               const float* __restrict__ bias, const float* __restrict__ addsrc,
               const float* __restrict__ rbf, const float* __restrict__ wrbf1,
               const float* __restrict__ wrbf2,
               float* __restrict__ out, int M)
{
    constexpr int MTILE = 128;
    constexpr int BK    = 32;
    constexpr int KT    = K / BK;
    constexpr int WST   = N + 8;         // (8tg+g)%32 distinct -> conflict-free
    constexpr int AST   = 36;            // 144B row = 9*16B, ldmatrix-aligned
    constexpr int WNN   = N / 4;
    constexpr int NTn   = WNN / 8;       // 4 for N=128, 2 for N=64
    constexpr int ABUF  = MTILE * AST;
    static_assert(N % 32 == 0 && K % BK == 0, "shape");

    extern __shared__ uint32_t smem[];
    uint32_t* Ws = smem;                 // [K][WST]
    uint32_t* As = Ws + K * WST;         // [2][128][AST]
    float*    w2s = (float*)(As + 2 * ABUF);
    float*    r8s = w2s + (RBF ? 1024 : 0);

    const int tid    = threadIdx.x;
    const int wid    = tid >> 5;
    const int lane   = tid & 31;
    const int g      = lane >> 2;
    const int tg     = lane & 3;
    const int warp_m = wid & 1;
    const int warp_n = wid >> 1;
    const int m0     = blockIdx.x * MTILE;

    // Load W (once, tf32, all K rows)
    #pragma unroll
    for (int u = 0; u < (K * N / 4) / 256; u++) {
        int idx = tid + u * 256;
        int kk = idx / (N / 4), nq = idx % (N / 4);
        float4 v = *reinterpret_cast<const float4*>(W + (size_t)kk * N + nq * 4);
        uint4 o = make_uint4(f2tf(v.x), f2tf(v.y), f2tf(v.z), f2tf(v.w));
        *reinterpret_cast<uint4*>(&Ws[kk * WST + nq * 4]) = o;
    }

    if (RBF) {
        #pragma unroll
        for (int u = 0; u < 4; u++) w2s[tid + u * 256] = wrbf2[tid + u * 256];
        #pragma unroll
        for (int u = 0; u < 4; u++) {
            int idx = tid + u * 256;
            int row = idx >> 3, jj = idx & 7;
            int grow = m0 + row;
            float s = 0.f;
            if (grow < M) {
                #pragma unroll
                for (int i = 0; i < C_NR; i++)
                    s += rbf[(size_t)grow * C_NR + i] * wrbf1[i * 8 + jj];
            }
            r8s[row * 8 + jj] = s;
        }
    }

    const int st_row = tid >> 3;
    const int st_kq  = tid & 7;
    float4 v[4];

    auto load_regs = [&](int k0) {
        #pragma unroll
        for (int u = 0; u < 4; u++) {
            int grow = m0 + st_row + u * 32;
            v[u] = (grow < M)
                ? *reinterpret_cast<const float4*>(A + (size_t)grow * K + k0 + st_kq * 4)
                : make_float4(0.f, 0.f, 0.f, 0.f);
        }
    };
    auto store_tile = [&](int buf) {
        uint32_t* dst = As + buf * ABUF;
        #pragma unroll
        for (int u = 0; u < 4; u++) {
            uint4 o = make_uint4(f2tf(v[u].x), f2tf(v[u].y), f2tf(v[u].z), f2tf(v[u].w));
            *reinterpret_cast<uint4*>(&dst[(st_row + u * 32) * AST + st_kq * 4]) = o;
        }
    };

    const uint32_t as_base = (uint32_t)__cvta_generic_to_shared(As);
    const int lrow_sm = lane & 15;
    const int lk_sm   = (lane >> 4) * 4;

    float c[4][NTn][4];
    #pragma unroll
    for (int mt = 0; mt < 4; mt++)
        #pragma unroll
        for (int nt = 0; nt < NTn; nt++)
            #pragma unroll
            for (int i = 0; i < 4; i++) c[mt][nt][i] = 0.f;

    load_regs(0);
    store_tile(0);
    __syncthreads();

    uint32_t af[2][4][4];
    uint32_t bf[2][NTn][2];

    for (int it = 0; it < KT; ++it) {
        const bool has_next = (it + 1 < KT);
        if (has_next) load_regs((it + 1) * BK);

        const uint32_t buf_b = as_base + (uint32_t)((it & 1) * ABUF) * 4u;
        const uint32_t* Wb = Ws + it * BK * WST;

        auto load_frags = [&](int k8, int pb) {
            #pragma unroll
            for (int mt = 0; mt < 4; mt++) {
                int row = warp_m * 64 + mt * 16 + lrow_sm;
                ldsm_x4(af[pb][mt], buf_b + (uint32_t)(row * AST + k8 + lk_sm) * 4u);
            }
            #pragma unroll
            for (int nt = 0; nt < NTn; nt++) {
                int cb = warp_n * WNN + nt * 8;
                bf[pb][nt][0] = Wb[(k8 + tg) * WST + cb + g];
                bf[pb][nt][1] = Wb[(k8 + tg + 4) * WST + cb + g];
            }
        };

        load_frags(0, 0);
        #pragma unroll
        for (int s = 0; s < BK / 8; s++) {
            const int cur = s & 1;
            if (s + 1 < BK / 8) load_frags((s + 1) * 8, cur ^ 1);
            #pragma unroll
            for (int nt = 0; nt < NTn; nt++)
                #pragma unroll
                for (int mt = 0; mt < 4; mt++)
                    mma_tf32(c[mt][nt], af[cur][mt], bf[cur][nt][0], bf[cur][nt][1]);
        }

        if (has_next) store_tile((it + 1) & 1);
        __syncthreads();
    }

    // Epilogue
    #pragma unroll
    for (int mt = 0; mt < 4; mt++) {
        #pragma unroll
        for (int half = 0; half < 2; half++) {
            int lrow = warp_m * 64 + mt * 16 + half * 8 + g;
            int grow = m0 + lrow;
            if (grow >= M) continue;
            #pragma unroll
            for (int nt = 0; nt < NTn; nt++) {
                int col = warp_n * WNN + nt * 8 + tg * 2;
                float v0 = c[mt][nt][half * 2 + 0];
                float v1 = c[mt][nt][half * 2 + 1];
                if (BIAS) { v0 += bias[col]; v1 += bias[col + 1]; }
                if (ACT)  { v0 = swishf(v0); v1 = swishf(v1); }
                if (RBF) {
                    float re0 = 0.f, re1 = 0.f;
                    #pragma unroll
                    for (int k = 0; k < 8; k++) {
                        float r = r8s[lrow * 8 + k];
                        re0 += r * w2s[k * 128 + col];
                        re1 += r * w2s[k * 128 + col + 1];
                    }
                    v0 *= re0; v1 *= re1;
                }
                if (ADD) {
                    float2 av = *reinterpret_cast<const float2*>(
                        addsrc + (size_t)grow * N + col);
                    v0 += av.x; v1 += av.y;
                }
                *reinterpret_cast<float2*>(out + (size_t)grow * N + col) =
                    make_float2(v0, v1);
            }
        }
    }
}

// ---------------------------------------------------------------------------
// Fused residual block: out = h + swish(swish(h@W1+b1)@W2+b2)
// 512 threads, 128-row tile. W1,W2 resident (tf32). t1 lives entirely in smem
// ([128][132] words; row stride 528B = 33*16B -> ldmatrix-aligned, conflict-
// free). GEMM2 has zero staging and zero mainloop syncs. In-place h==out safe.
// ---------------------------------------------------------------------------
__global__ __launch_bounds__(512, 1)
void res2_k(const float* __restrict__ A, const float* __restrict__ W1,
            const float* __restrict__ b1, const float* __restrict__ W2,
            const float* __restrict__ b2, float* __restrict__ out, int M)
{
    constexpr int KD   = 128;
    constexpr int ND   = 128;
    constexpr int WST  = 136;   // (8tg+g)%32 distinct -> conflict-free B-LDS
    constexpr int AST  = 36;    // staged-A row stride
    constexpr int AST2 = 132;   // t1 row stride: 528B = 33*16B aligned; banks 4r+c distinct

    extern __shared__ uint32_t smem[];
    uint32_t* W1s = smem;                    // [128][136]
    uint32_t* W2s = W1s + 128 * WST;         // [128][136]
    uint32_t* T1s = W2s + 128 * WST;         // [128][132]
    uint32_t* As  = T1s + 128 * AST2;        // [128][36]

    const int tid    = threadIdx.x;
    const int wid    = tid >> 5;             // 0..15
    const int lane   = tid & 31;
    const int g      = lane >> 2;
    const int tg     = lane & 3;
    const int warp_m = wid & 3;              // 32-row groups
    const int warp_n = wid >> 2;             // 32-col groups
    const int m0     = blockIdx.x * 128;

    // Load W1, W2 (tf32): 4096 float4 each, 8 per thread
    #pragma unroll
    for (int u = 0; u < 8; u++) {
        int idx = tid + u * 512;
        int kk = idx >> 5, nq = idx & 31;
        float4 a = *reinterpret_cast<const float4*>(W1 + (size_t)kk * ND + nq * 4);
        *reinterpret_cast<uint4*>(&W1s[kk * WST + nq * 4]) =
            make_uint4(f2tf(a.x), f2tf(a.y), f2tf(a.z), f2tf(a.w));
        float4 b = *reinterpret_cast<const float4*>(W2 + (size_t)kk * ND + nq * 4);
        *reinterpret_cast<uint4*>(&W2s[kk * WST + nq * 4]) =
            make_uint4(f2tf(b.x), f2tf(b.y), f2tf(b.z), f2tf(b.w));
    }

    const uint32_t as_base = (uint32_t)__cvta_generic_to_shared(As);
    const uint32_t t1_base = (uint32_t)__cvta_generic_to_shared(T1s);
    const int lrow_sm = lane & 15;
    const int lk_sm   = (lane >> 4) * 4;

    float c[2][4][4];
    #pragma unroll
    for (int mt = 0; mt < 2; mt++)
        #pragma unroll
        for (int nt = 0; nt < 4; nt++)
            #pragma unroll
            for (int i = 0; i < 4; i++) c[mt][nt][i] = 0.f;

    uint32_t af[2][2][4];
    uint32_t bf[2][4][2];

    // ---------------- GEMM1: t1 = swish(h @ W1 + b1) ----------------
    for (int it = 0; it < 4; ++it) {
        __syncthreads();   // first: covers W staging; later: protects As readers
        // Stage A tile [128][32]: 1024 float4 / 512 threads = 2 each
        #pragma unroll
        for (int u = 0; u < 2; u++) {
            int idx = tid + u * 512;
            int row = idx >> 3, kq = idx & 7;
            int grow = m0 + row;
            float4 v = (grow < M)
                ? *reinterpret_cast<const float4*>(A + (size_t)grow * KD + it * 32 + kq * 4)
                : make_float4(0.f, 0.f, 0.f, 0.f);
            *reinterpret_cast<uint4*>(&As[row * AST + kq * 4]) =
                make_uint4(f2tf(v.x), f2tf(v.y), f2tf(v.z), f2tf(v.w));
        }
        __syncthreads();

        const uint32_t* Wb = W1s + it * 32 * WST;
        auto load_f1 = [&](int k8, int pb) {
            #pragma unroll
            for (int mt = 0; mt < 2; mt++) {
                int row = warp_m * 32 + mt * 16 + lrow_sm;
                ldsm_x4(af[pb][mt], as_base + (uint32_t)(row * AST + k8 + lk_sm) * 4u);
            }
            #pragma unroll
            for (int nt = 0; nt < 4; nt++) {
                int cb = warp_n * 32 + nt * 8;
                bf[pb][nt][0] = Wb[(k8 + tg) * WST + cb + g];
                bf[pb][nt][1] = Wb[(k8 + tg + 4) * WST + cb + g];
            }
        };
        load_f1(0, 0);
        #pragma unroll
        for (int s = 0; s < 4; s++) {
            const int cur = s & 1;
            if (s + 1 < 4) load_f1((s + 1) * 8, cur ^ 1);
            #pragma unroll
            for (int nt = 0; nt < 4; nt++)
                #pragma unroll
                for (int mt = 0; mt < 2; mt++)
                    mma_tf32(c[mt][nt], af[cur][mt], bf[cur][nt][0], bf[cur][nt][1]);
        }
    }
    __syncthreads();   // all reads of As done; order T1s writes after mainloop

    // Epilogue 1: t1 = swish(c + b1) -> T1s (tf32)
    #pragma unroll
    for (int mt = 0; mt < 2; mt++) {
        #pragma unroll
        for (int half = 0; half < 2; half++) {
            int lrow = warp_m * 32 + mt * 16 + half * 8 + g;
            #pragma unroll
            for (int nt = 0; nt < 4; nt++) {
                int col = warp_n * 32 + nt * 8 + tg * 2;
                float v0 = swishf(c[mt][nt][half * 2 + 0] + b1[col]);
                float v1 = swishf(c[mt][nt][half * 2 + 1] + b1[col + 1]);
                uint2 o = make_uint2(f2tf(v0), f2tf(v1));
                *reinterpret_cast<uint2*>(&T1s[lrow * AST2 + col]) = o;
            }
        }
    }
    __syncthreads();

    // ---------------- GEMM2: out = h + swish(t1 @ W2 + b2) ----------------
    #pragma unroll
    for (int mt = 0; mt < 2; mt++)
        #pragma unroll
        for (int nt = 0; nt < 4; nt++)
            #pragma unroll
            for (int i = 0; i < 4; i++) c[mt][nt][i] = 0.f;

    auto load_f2 = [&](int k8, int pb) {
        #pragma unroll
        for (int mt = 0; mt < 2; mt++) {
            int row = warp_m * 32 + mt * 16 + lrow_sm;
            ldsm_x4(af[pb][mt], t1_base + (uint32_t)(row * AST2 + k8 + lk_sm) * 4u);
        }
        #pragma unroll
        for (int nt = 0; nt < 4; nt++) {
            int cb = warp_n * 32 + nt * 8;
            bf[pb][nt][0] = W2s[(k8 + tg) * WST + cb + g];
            bf[pb][nt][1] = W2s[(k8 + tg + 4) * WST + cb + g];
        }
    };
    load_f2(0, 0);
    #pragma unroll
    for (int s = 0; s < 16; s++) {
        const int cur = s & 1;
        if (s + 1 < 16) load_f2((s + 1) * 8, cur ^ 1);
        #pragma unroll
        for (int nt = 0; nt < 4; nt++)
            #pragma unroll
            for (int mt = 0; mt < 2; mt++)
                mma_tf32(c[mt][nt], af[cur][mt], bf[cur][nt][0], bf[cur][nt][1]);
    }

    // Epilogue 2: out = h + swish(c + b2). Each thread re-reads exactly the h
    // elements it writes (in-place safe; block touches only its own rows).
    #pragma unroll
    for (int mt = 0; mt < 2; mt++) {
        #pragma unroll
        for (int half = 0; half < 2; half++) {
            int lrow = warp_m * 32 + mt * 16 + half * 8 + g;
            int grow = m0 + lrow;
            if (grow >= M) continue;
            #pragma unroll
            for (int nt = 0; nt < 4; nt++) {
                int col = warp_n * 32 + nt * 8 + tg * 2;
                float2 hv = *reinterpret_cast<const float2*>(A + (size_t)grow * ND + col);
                float v0 = hv.x + swishf(c[mt][nt][half * 2 + 0] + b2[col]);
                float v1 = hv.y + swishf(c[mt][nt][half * 2 + 1] + b2[col + 1]);
                *reinterpret_cast<float2*>(out + (size_t)grow * ND + col) =
                    make_float2(v0, v1);
            }
        }
    }
}

// ---------------------------------------------------------------------------
// Triplet kernel (unchanged)
// ---------------------------------------------------------------------------
__global__ __launch_bounds__(256)
void trip_k(const float* __restrict__ sbf, const int* __restrict__ idx_kj,
            const int* __restrict__ idx_ji, const float* __restrict__ w1,
            const float* __restrict__ w2, const float* __restrict__ xkjd,
            float* __restrict__ agg, int T)
{
    __shared__ float w1s[C_NSBF * C_BAS];
    __shared__ float w2s[C_BAS * C_INT];
    __shared__ float sbfs[16][C_NSBF];
    __shared__ float s8s[16][C_BAS];

    const int tid = threadIdx.x;
    for (int i = tid; i < C_NSBF * C_BAS; i += 256) w1s[i] = w1[i];
    for (int i = tid; i < C_BAS * C_INT; i += 256) w2s[i] = w2[i];

    const int local = tid >> 4;
    const int lane  = tid & 15;
    const long t = (long)blockIdx.x * 16 + local;
    const bool valid = (t < T);

    if (valid) {
        const float* sp = sbf + t * C_NSBF;
        for (int i = lane; i < C_NSBF; i += 16) sbfs[local][i] = sp[i];
    }
    __syncthreads();

    if (valid && lane < C_BAS) {
        float s = 0.f;
        #pragma unroll
        for (int i = 0; i < C_NSBF; i++) s += sbfs[local][i] * w1s[i * C_BAS + lane];
        s8s[local][lane] = s;
    }
    __syncthreads();

    if (valid) {
        const int ikj = idx_kj[t];
        const int iji = idx_ji[t];
        float4 gv = *reinterpret_cast<const float4*>(xkjd + (size_t)ikj * C_INT + lane * 4);
        float se[4];
        #pragma unroll
        for (int cc = 0; cc < 4; cc++) {
            float s = 0.f;
            #pragma unroll
            for (int k = 0; k < C_BAS; k++)
                s += s8s[local][k] * w2s[k * C_INT + lane * 4 + cc];
            se[cc] = s;
        }
        float mx = gv.x * se[0], my = gv.y * se[1], mz = gv.z * se[2], mw = gv.w * se[3];
        float* p = agg + (size_t)iji * C_INT + lane * 4;
        asm volatile("red.global.add.v4.f32 [%0], {%1,%2,%3,%4};"
                     :: "l"(p), "f"(mx), "f"(my), "f"(mz), "f"(mw) : "memory");
    }
}

__global__ __launch_bounds__(256)
void zero_k(float4* __restrict__ p, int n4)
{
    int i = blockIdx.x * blockDim.x + threadIdx.x;
    if (i < n4) p[i] = make_float4(0.f, 0.f, 0.f, 0.f);
}

// ---------------------------------------------------------------------------
static inline int gemm5_smem_bytes(int N, int K, bool rbf) {
    int wst = N + 8;
    int words = K * wst + 2 * 128 * 36 + (rbf ? 2048 : 0);
    return words * 4;
}
static inline int res2_smem_bytes() {
    return (2 * 128 * 136 + 128 * 132 + 128 * 36) * 4;   // 225280
}

extern "C" void kernel_launch(void* const* d_in, const int* in_sizes, int n_in,
                              void* d_out, int out_size)
{
    const float* x       = (const float*)d_in[0];
    const float* rbf     = (const float*)d_in[1];
    const float* sbf     = (const float*)d_in[2];
    const int*   idx_kj  = (const int*)  d_in[3];
    const int*   idx_ji  = (const int*)  d_in[4];
    const float* w_rbf1  = (const float*)d_in[5];
    const float* w_rbf2  = (const float*)d_in[6];
    const float* w_sbf1  = (const float*)d_in[7];
    const float* w_sbf2  = (const float*)d_in[8];
    const float* w_kj    = (const float*)d_in[9];
    const float* b_kj    = (const float*)d_in[10];
    const float* w_ji    = (const float*)d_in[11];
    const float* b_ji    = (const float*)d_in[12];
    const float* w_down  = (const float*)d_in[13];
    const float* w_up    = (const float*)d_in[14];
    const float* rb0_w1  = (const float*)d_in[15];
    const float* rb0_b1  = (const float*)d_in[16];
    const float* rb0_w2  = (const float*)d_in[17];
    const float* rb0_b2  = (const float*)d_in[18];
    const float* w_lin   = (const float*)d_in[19];
    const float* b_lin   = (const float*)d_in[20];
    const float* ra0_w1  = (const float*)d_in[21];
    const float* ra0_b1  = (const float*)d_in[22];
    const float* ra0_w2  = (const float*)d_in[23];
    const float* ra0_b2  = (const float*)d_in[24];
    const float* ra1_w1  = (const float*)d_in[25];
    const float* ra1_b1  = (const float*)d_in[26];
    const float* ra1_w2  = (const float*)d_in[27];
    const float* ra1_b2  = (const float*)d_in[28];
    float* out = (float*)d_out;

    const int E = in_sizes[0] / C_HID;  // 200000
    const int T = in_sizes[3];          // 2000000

    float *bufA, *bufB, *bufC, *bufD;
    cudaGetSymbolAddress((void**)&bufA, g_bufA);
    cudaGetSymbolAddress((void**)&bufB, g_bufB);
    cudaGetSymbolAddress((void**)&bufC, g_bufC);
    cudaGetSymbolAddress((void**)&bufD, g_bufD);

    const int gE = (E + 127) / 128;

    const int smem_std  = gemm5_smem_bytes(128, 128, false); // 106496
    const int smem_rbf  = gemm5_smem_bytes(128, 128, true);  // 114688
    const int smem_down = gemm5_smem_bytes( 64, 128, false); //  73728
    const int smem_up   = gemm5_smem_bytes(128,  64, false); //  71680
    const int smem_res  = res2_smem_bytes();                 // 225280

    cudaFuncSetAttribute(mma_gemm5<128,128,true ,true,false,false>,
                         cudaFuncAttributeMaxDynamicSharedMemorySize, smem_std);
    cudaFuncSetAttribute(mma_gemm5<128,128,true ,true,true ,false>,
                         cudaFuncAttributeMaxDynamicSharedMemorySize, smem_std);
    cudaFuncSetAttribute(mma_gemm5<128,128,true ,true,false,true >,
                         cudaFuncAttributeMaxDynamicSharedMemorySize, smem_rbf);
    cudaFuncSetAttribute(mma_gemm5< 64,128,false,true,false,false>,
                         cudaFuncAttributeMaxDynamicSharedMemorySize, smem_down);
    cudaFuncSetAttribute(mma_gemm5<128, 64,false,true,true ,false>,
                         cudaFuncAttributeMaxDynamicSharedMemorySize, smem_up);
    cudaFuncSetAttribute(res2_k,
                         cudaFuncAttributeMaxDynamicSharedMemorySize, smem_res);

    // 0) agg = 0
    {
        int n4 = E * C_INT / 4;
        zero_k<<<(n4 + 255) / 256, 256>>>((float4*)bufD, n4);
    }
    // 1) x_ji = swish(x @ w_ji + b_ji)                       -> bufA
    mma_gemm5<128,128,true,true,false,false><<<gE,256,smem_std>>>(x, w_ji, b_ji, nullptr, nullptr, nullptr, nullptr, bufA, E);
    // 2) t = swish(x @ w_kj + b_kj) * rbf_e                  -> bufB
    mma_gemm5<128,128,true,true,false,true ><<<gE,256,smem_rbf>>>(x, w_kj, b_kj, nullptr, rbf, w_rbf1, w_rbf2, bufB, E);
    // 3) xkjd = swish(t @ w_down)                            -> bufC
    mma_gemm5< 64,128,false,true,false,false><<<gE,256,smem_down>>>(bufB, w_down, nullptr, nullptr, nullptr, nullptr, nullptr, bufC, E);
    // 4) triplet gather/scale/scatter                        -> bufD
    trip_k<<<(T + 15) / 16, 256>>>(sbf, idx_kj, idx_ji, w_sbf1, w_sbf2, bufC, bufD, T);
    // 5) h = swish(agg @ w_up) + x_ji                        -> bufB
    mma_gemm5<128, 64,false,true,true ,false><<<gE,256,smem_up>>>(bufD, w_up, nullptr, bufA, nullptr, nullptr, nullptr, bufB, E);
    // 6) rb0 (fused residual)                                -> bufB
    res2_k<<<gE,512,smem_res>>>(bufB, rb0_w1, rb0_b1, rb0_w2, rb0_b2, bufB, E);
    // 7) h = swish(h @ w_lin + b_lin) + x                    -> bufB
    mma_gemm5<128,128,true,true,true ,false><<<gE,256,smem_std>>>(bufB, w_lin, b_lin, x, nullptr, nullptr, nullptr, bufB, E);
    // 8) ra0 (fused residual)                                -> bufB
    res2_k<<<gE,512,smem_res>>>(bufB, ra0_w1, ra0_b1, ra0_w2, ra0_b2, bufB, E);
    // 9) ra1 (fused residual, writes final output)           -> out
    res2_k<<<gE,512,smem_res>>>(bufB, ra1_w1, ra1_b1, ra1_w2, ra1_b2, out, E);

    (void)n_in; (void)out_size; (void)in_sizes;
}

// round 16
// speedup vs baseline: 1.1803x; 1.1803x over previous
#include <cuda_runtime.h>
#include <cstdint>
#include <cstddef>

// Problem constants
#define C_HID 128
#define C_INT 64
#define C_BAS 8
#define C_NR 6
#define C_NSBF 42      // NS*NR = 7*6
#define C_NE 200000
#define C_NT 2000000

// Scratch buffers (device globals; no allocation allowed)
__device__ __align__(128) float g_bufA[C_NE * C_HID];
__device__ __align__(128) float g_bufB[C_NE * C_HID];
__device__ __align__(128) float g_bufC[C_NE * C_INT];
__device__ __align__(128) float g_bufD[C_NE * C_INT];
__device__ __align__(128) float g_bufS[(size_t)C_NT * C_BAS];   // s8 = sbf @ w_sbf1

__device__ __forceinline__ float swishf(float v) {
    return v / (1.0f + __expf(-v));
}

__device__ __forceinline__ uint32_t f2tf(float f) {
    uint32_t r;
    asm("cvt.rna.tf32.f32 %0, %1;" : "=r"(r) : "f"(f));
    return r;
}

__device__ __forceinline__ void mma_tf32(float c[4], const uint32_t a[4],
                                         uint32_t b0, uint32_t b1) {
    asm volatile(
        "mma.sync.aligned.m16n8k8.row.col.f32.tf32.tf32.f32 "
        "{%0,%1,%2,%3}, {%4,%5,%6,%7}, {%8,%9}, {%0,%1,%2,%3};"
        : "+f"(c[0]), "+f"(c[1]), "+f"(c[2]), "+f"(c[3])
        : "r"(a[0]), "r"(a[1]), "r"(a[2]), "r"(a[3]), "r"(b0), "r"(b1));
}

__device__ __forceinline__ void ldsm_x4(uint32_t a[4], uint32_t byte_addr) {
    asm volatile(
        "ldmatrix.sync.aligned.m8n8.x4.shared.b16 {%0,%1,%2,%3}, [%4];"
        : "=r"(a[0]), "=r"(a[1]), "=r"(a[2]), "=r"(a[3])
        : "r"(byte_addr));
}

// ---------------------------------------------------------------------------
// TF32 tensor-core GEMM v4 (exact R13 version — best measured; NO prefetch,
// which regressed in R15: regs 79->114, occ 34.7->23.7).
// W fully resident; A double-buffered; ldmatrix.x4 A-fragments; 2m x 4n warps.
// epi: (+bias) -> (swish) -> (*rbf_e) -> (+addsrc). In-place A==out safe.
// ---------------------------------------------------------------------------
template<int N, int K, bool BIAS, bool ACT, bool ADD, bool RBF>
__global__ __launch_bounds__(256)
void mma_gemm4(const float* __restrict__ A, const float* __restrict__ W,
               const float* __restrict__ bias, const float* __restrict__ addsrc,
               const float* __restrict__ rbf, const float* __restrict__ wrbf1,
               const float* __restrict__ wrbf2,
               float* __restrict__ out, int M)
{
    constexpr int MTILE = 128;
    constexpr int BK    = 32;
    constexpr int KT    = K / BK;
    constexpr int WST   = N + 8;
    constexpr int AST   = 36;
    constexpr int WNN   = N / 4;
    constexpr int NTn   = WNN / 8;
    constexpr int ABUF  = MTILE * AST;
    static_assert(N % 32 == 0 && K % BK == 0, "shape");

    extern __shared__ uint32_t smem[];
    uint32_t* Ws = smem;                 // [K][WST]
    uint32_t* As = Ws + K * WST;         // [2][128][AST]
    float*    w2s = (float*)(As + 2 * ABUF);
    float*    r8s = w2s + (RBF ? 1024 : 0);

    const int tid    = threadIdx.x;
    const int wid    = tid >> 5;
    const int lane   = tid & 31;
    const int g      = lane >> 2;
    const int tg     = lane & 3;
    const int warp_m = wid & 1;
    const int warp_n = wid >> 1;
    const int m0     = blockIdx.x * MTILE;

    #pragma unroll
    for (int u = 0; u < (K * N / 4) / 256; u++) {
        int idx = tid + u * 256;
        int kk = idx / (N / 4), nq = idx % (N / 4);
        float4 v = *reinterpret_cast<const float4*>(W + (size_t)kk * N + nq * 4);
        uint4 o = make_uint4(f2tf(v.x), f2tf(v.y), f2tf(v.z), f2tf(v.w));
        *reinterpret_cast<uint4*>(&Ws[kk * WST + nq * 4]) = o;
    }

    if (RBF) {
        #pragma unroll
        for (int u = 0; u < 4; u++) w2s[tid + u * 256] = wrbf2[tid + u * 256];
        #pragma unroll
        for (int u = 0; u < 4; u++) {
            int idx = tid + u * 256;
            int row = idx >> 3, jj = idx & 7;
            int grow = m0 + row;
            float s = 0.f;
            if (grow < M) {
                #pragma unroll
                for (int i = 0; i < C_NR; i++)
                    s += rbf[(size_t)grow * C_NR + i] * wrbf1[i * 8 + jj];
            }
            r8s[row * 8 + jj] = s;
        }
    }

    const int st_row = tid >> 3;
    const int st_kq  = tid & 7;
    float4 v[4];

    auto load_regs = [&](int k0) {
        #pragma unroll
        for (int u = 0; u < 4; u++) {
            int grow = m0 + st_row + u * 32;
            v[u] = (grow < M)
                ? *reinterpret_cast<const float4*>(A + (size_t)grow * K + k0 + st_kq * 4)
                : make_float4(0.f, 0.f, 0.f, 0.f);
        }
    };
    auto store_tile = [&](int buf) {
        uint32_t* dst = As + buf * ABUF;
        #pragma unroll
        for (int u = 0; u < 4; u++) {
            uint4 o = make_uint4(f2tf(v[u].x), f2tf(v[u].y), f2tf(v[u].z), f2tf(v[u].w));
            *reinterpret_cast<uint4*>(&dst[(st_row + u * 32) * AST + st_kq * 4]) = o;
        }
    };

    const uint32_t as_base = (uint32_t)__cvta_generic_to_shared(As);
    const int lrow_sm = lane & 15;
    const int lk_sm   = (lane >> 4) * 4;

    float c[4][NTn][4];
    #pragma unroll
    for (int mt = 0; mt < 4; mt++)
        #pragma unroll
        for (int nt = 0; nt < NTn; nt++)
            #pragma unroll
            for (int i = 0; i < 4; i++) c[mt][nt][i] = 0.f;

    load_regs(0);
    store_tile(0);
    __syncthreads();

    for (int it = 0; it < KT; ++it) {
        const bool has_next = (it + 1 < KT);
        if (has_next) load_regs((it + 1) * BK);

        const uint32_t buf_b = as_base + (uint32_t)((it & 1) * ABUF) * 4u;
        const uint32_t* Wb = Ws + it * BK * WST;
        #pragma unroll
        for (int k8 = 0; k8 < BK; k8 += 8) {
            uint32_t a[4][4];
            #pragma unroll
            for (int mt = 0; mt < 4; mt++) {
                int row = warp_m * 64 + mt * 16 + lrow_sm;
                ldsm_x4(a[mt], buf_b + (uint32_t)(row * AST + k8 + lk_sm) * 4u);
            }
            #pragma unroll
            for (int nt = 0; nt < NTn; nt++) {
                int cb = warp_n * WNN + nt * 8;
                uint32_t b0 = Wb[(k8 + tg) * WST + cb + g];
                uint32_t b1 = Wb[(k8 + tg + 4) * WST + cb + g];
                #pragma unroll
                for (int mt = 0; mt < 4; mt++)
                    mma_tf32(c[mt][nt], a[mt], b0, b1);
            }
        }

        if (has_next) store_tile((it + 1) & 1);
        __syncthreads();
    }

    #pragma unroll
    for (int mt = 0; mt < 4; mt++) {
        #pragma unroll
        for (int half = 0; half < 2; half++) {
            int lrow = warp_m * 64 + mt * 16 + half * 8 + g;
            int grow = m0 + lrow;
            if (grow >= M) continue;
            #pragma unroll
            for (int nt = 0; nt < NTn; nt++) {
                int col = warp_n * WNN + nt * 8 + tg * 2;
                float v0 = c[mt][nt][half * 2 + 0];
                float v1 = c[mt][nt][half * 2 + 1];
                if (BIAS) { v0 += bias[col]; v1 += bias[col + 1]; }
                if (ACT)  { v0 = swishf(v0); v1 = swishf(v1); }
                if (RBF) {
                    float re0 = 0.f, re1 = 0.f;
                    #pragma unroll
                    for (int k = 0; k < 8; k++) {
                        float r = r8s[lrow * 8 + k];
                        re0 += r * w2s[k * 128 + col];
                        re1 += r * w2s[k * 128 + col + 1];
                    }
                    v0 *= re0; v1 *= re1;
                }
                if (ADD) {
                    float2 av = *reinterpret_cast<const float2*>(
                        addsrc + (size_t)grow * N + col);
                    v0 += av.x; v1 += av.y;
                }
                *reinterpret_cast<float2*>(out + (size_t)grow * N + col) =
                    make_float2(v0, v1);
            }
        }
    }
}

// ---------------------------------------------------------------------------
// sbfe_k: dense streaming projection s8[T,8] = sbf[T,42] @ w1[42,8].
// One thread per triplet row; float2 loads (rows are 8B-aligned: 42*4=168B).
// No barriers in the hot path; pure streaming (~400 MB total traffic).
// ---------------------------------------------------------------------------
__global__ __launch_bounds__(256)
void sbfe_k(const float* __restrict__ sbf, const float* __restrict__ w1,
            float* __restrict__ s8, int T)
{
    __shared__ float w1s[C_NSBF * C_BAS];
    const int tid = threadIdx.x;
    for (int i = tid; i < C_NSBF * C_BAS; i += 256) w1s[i] = w1[i];
    __syncthreads();

    long t = (long)blockIdx.x * 256 + tid;
    if (t >= T) return;

    const float2* sp = reinterpret_cast<const float2*>(sbf + t * C_NSBF);
    float sv[C_NSBF];
    #pragma unroll
    for (int i = 0; i < C_NSBF / 2; i++) {
        float2 p = sp[i];
        sv[2 * i] = p.x; sv[2 * i + 1] = p.y;
    }

    float acc[C_BAS];
    #pragma unroll
    for (int j = 0; j < C_BAS; j++) acc[j] = 0.f;
    #pragma unroll
    for (int i = 0; i < C_NSBF; i++) {
        #pragma unroll
        for (int j = 0; j < C_BAS; j++)
            acc[j] += sv[i] * w1s[i * C_BAS + j];
    }
    float4* dst = reinterpret_cast<float4*>(s8 + t * C_BAS);
    dst[0] = make_float4(acc[0], acc[1], acc[2], acc[3]);
    dst[1] = make_float4(acc[4], acc[5], acc[6], acc[7]);
}

// ---------------------------------------------------------------------------
// trip2_k: msg = xkjd[idx_kj] * (s8 @ w2); agg[idx_ji] += msg.
// 16 lanes per triplet; w2 in smem; NO per-triplet barriers or smem staging.
// ---------------------------------------------------------------------------
__global__ __launch_bounds__(256)
void trip2_k(const float* __restrict__ s8, const int* __restrict__ idx_kj,
             const int* __restrict__ idx_ji, const float* __restrict__ w2,
             const float* __restrict__ xkjd, float* __restrict__ agg, int T)
{
    __shared__ float w2s[C_BAS * C_INT];
    const int tid = threadIdx.x;
    for (int i = tid; i < C_BAS * C_INT; i += 256) w2s[i] = w2[i];
    __syncthreads();

    const int local = tid >> 4;
    const int lane  = tid & 15;
    long t = (long)blockIdx.x * 16 + local;
    if (t >= T) return;

    const int ikj = idx_kj[t];
    const int iji = idx_ji[t];
    float4 s0 = *reinterpret_cast<const float4*>(s8 + t * C_BAS);
    float4 s1 = *reinterpret_cast<const float4*>(s8 + t * C_BAS + 4);
    float4 gv = *reinterpret_cast<const float4*>(xkjd + (size_t)ikj * C_INT + lane * 4);

    float se[4];
    #pragma unroll
    for (int c = 0; c < 4; c++) {
        int col = lane * 4 + c;
        se[c] = s0.x * w2s[0 * C_INT + col] + s0.y * w2s[1 * C_INT + col]
              + s0.z * w2s[2 * C_INT + col] + s0.w * w2s[3 * C_INT + col]
              + s1.x * w2s[4 * C_INT + col] + s1.y * w2s[5 * C_INT + col]
              + s1.z * w2s[6 * C_INT + col] + s1.w * w2s[7 * C_INT + col];
    }
    float mx = gv.x * se[0], my = gv.y * se[1], mz = gv.z * se[2], mw = gv.w * se[3];
    float* p = agg + (size_t)iji * C_INT + lane * 4;
    asm volatile("red.global.add.v4.f32 [%0], {%1,%2,%3,%4};"
                 :: "l"(p), "f"(mx), "f"(my), "f"(mz), "f"(mw) : "memory");
}

__global__ __launch_bounds__(256)
void zero_k(float4* __restrict__ p, int n4)
{
    int i = blockIdx.x * blockDim.x + threadIdx.x;
    if (i < n4) p[i] = make_float4(0.f, 0.f, 0.f, 0.f);
}

// ---------------------------------------------------------------------------
static inline int gemm4_smem_bytes(int N, int K, bool rbf) {
    int wst = N + 8;
    int words = K * wst + 2 * 128 * 36 + (rbf ? 2048 : 0);
    return words * 4;
}

extern "C" void kernel_launch(void* const* d_in, const int* in_sizes, int n_in,
                              void* d_out, int out_size)
{
    const float* x       = (const float*)d_in[0];
    const float* rbf     = (const float*)d_in[1];
    const float* sbf     = (const float*)d_in[2];
    const int*   idx_kj  = (const int*)  d_in[3];
    const int*   idx_ji  = (const int*)  d_in[4];
    const float* w_rbf1  = (const float*)d_in[5];
    const float* w_rbf2  = (const float*)d_in[6];
    const float* w_sbf1  = (const float*)d_in[7];
    const float* w_sbf2  = (const float*)d_in[8];
    const float* w_kj    = (const float*)d_in[9];
    const float* b_kj    = (const float*)d_in[10];
    const float* w_ji    = (const float*)d_in[11];
    const float* b_ji    = (const float*)d_in[12];
    const float* w_down  = (const float*)d_in[13];
    const float* w_up    = (const float*)d_in[14];
    const float* rb0_w1  = (const float*)d_in[15];
    const float* rb0_b1  = (const float*)d_in[16];
    const float* rb0_w2  = (const float*)d_in[17];
    const float* rb0_b2  = (const float*)d_in[18];
    const float* w_lin   = (const float*)d_in[19];
    const float* b_lin   = (const float*)d_in[20];
    const float* ra0_w1  = (const float*)d_in[21];
    const float* ra0_b1  = (const float*)d_in[22];
    const float* ra0_w2  = (const float*)d_in[23];
    const float* ra0_b2  = (const float*)d_in[24];
    const float* ra1_w1  = (const float*)d_in[25];
    const float* ra1_b1  = (const float*)d_in[26];
    const float* ra1_w2  = (const float*)d_in[27];
    const float* ra1_b2  = (const float*)d_in[28];
    float* out = (float*)d_out;

    const int E = in_sizes[0] / C_HID;  // 200000
    const int T = in_sizes[3];          // 2000000

    float *bufA, *bufB, *bufC, *bufD, *bufS;
    cudaGetSymbolAddress((void**)&bufA, g_bufA);
    cudaGetSymbolAddress((void**)&bufB, g_bufB);
    cudaGetSymbolAddress((void**)&bufC, g_bufC);
    cudaGetSymbolAddress((void**)&bufD, g_bufD);
    cudaGetSymbolAddress((void**)&bufS, g_bufS);

    const int gE = (E + 127) / 128;

    const int smem_std  = gemm4_smem_bytes(128, 128, false); // 106496
    const int smem_rbf  = gemm4_smem_bytes(128, 128, true);  // 114688
    const int smem_down = gemm4_smem_bytes( 64, 128, false); //  73728
    const int smem_up   = gemm4_smem_bytes(128,  64, false); //  71680

    cudaFuncSetAttribute(mma_gemm4<128,128,true ,true,false,false>,
                         cudaFuncAttributeMaxDynamicSharedMemorySize, smem_std);
    cudaFuncSetAttribute(mma_gemm4<128,128,true ,true,true ,false>,
                         cudaFuncAttributeMaxDynamicSharedMemorySize, smem_std);
    cudaFuncSetAttribute(mma_gemm4<128,128,true ,true,false,true >,
                         cudaFuncAttributeMaxDynamicSharedMemorySize, smem_rbf);
    cudaFuncSetAttribute(mma_gemm4< 64,128,false,true,false,false>,
                         cudaFuncAttributeMaxDynamicSharedMemorySize, smem_down);
    cudaFuncSetAttribute(mma_gemm4<128, 64,false,true,true ,false>,
                         cudaFuncAttributeMaxDynamicSharedMemorySize, smem_up);

    // 0) s8 = sbf @ w_sbf1 (independent of edge chain; launched first)
    sbfe_k<<<(T + 255) / 256, 256>>>(sbf, w_sbf1, bufS, T);
    // 1) agg = 0
    {
        int n4 = E * C_INT / 4;
        zero_k<<<(n4 + 255) / 256, 256>>>((float4*)bufD, n4);
    }
    // 2) x_ji = swish(x @ w_ji + b_ji)                       -> bufA
    mma_gemm4<128,128,true,true,false,false><<<gE,256,smem_std>>>(x, w_ji, b_ji, nullptr, nullptr, nullptr, nullptr, bufA, E);
    // 3) t = swish(x @ w_kj + b_kj) * rbf_e                  -> bufB
    mma_gemm4<128,128,true,true,false,true ><<<gE,256,smem_rbf>>>(x, w_kj, b_kj, nullptr, rbf, w_rbf1, w_rbf2, bufB, E);
    // 4) xkjd = swish(t @ w_down)                            -> bufC
    mma_gemm4< 64,128,false,true,false,false><<<gE,256,smem_down>>>(bufB, w_down, nullptr, nullptr, nullptr, nullptr, nullptr, bufC, E);
    // 5) triplet gather/scale/scatter                        -> bufD
    trip2_k<<<(T + 15) / 16, 256>>>(bufS, idx_kj, idx_ji, w_sbf2, bufC, bufD, T);
    // 6) h = swish(agg @ w_up) + x_ji                        -> bufB
    mma_gemm4<128, 64,false,true,true ,false><<<gE,256,smem_up>>>(bufD, w_up, nullptr, bufA, nullptr, nullptr, nullptr, bufB, E);
    // 7) rb0
    mma_gemm4<128,128,true,true,false,false><<<gE,256,smem_std>>>(bufB, rb0_w1, rb0_b1, nullptr, nullptr, nullptr, nullptr, bufA, E);
    mma_gemm4<128,128,true,true,true ,false><<<gE,256,smem_std>>>(bufA, rb0_w2, rb0_b2, bufB, nullptr, nullptr, nullptr, bufB, E);
    // 8) h = swish(h @ w_lin + b_lin) + x
    mma_gemm4<128,128,true,true,true ,false><<<gE,256,smem_std>>>(bufB, w_lin, b_lin, x, nullptr, nullptr, nullptr, bufB, E);
    // 9) ra0
    mma_gemm4<128,128,true,true,false,false><<<gE,256,smem_std>>>(bufB, ra0_w1, ra0_b1, nullptr, nullptr, nullptr, nullptr, bufA, E);
    mma_gemm4<128,128,true,true,true ,false><<<gE,256,smem_std>>>(bufA, ra0_w2, ra0_b2, bufB, nullptr, nullptr, nullptr, bufB, E);
    // 10) ra1 (second GEMM writes final output)
    mma_gemm4<128,128,true,true,false,false><<<gE,256,smem_std>>>(bufB, ra1_w1, ra1_b1, nullptr, nullptr, nullptr, nullptr, bufA, E);
    mma_gemm4<128,128,true,true,true ,false><<<gE,256,smem_std>>>(bufA, ra1_w2, ra1_b2, bufB, nullptr, nullptr, nullptr, out, E);

    (void)n_in; (void)out_size; (void)in_sizes;
}